// round 7
// baseline (speedup 1.0000x reference)
#include <cuda_runtime.h>
#include <math.h>

// ---------------- problem constants ----------------
#define NN 100000
#define NE 1600000
#define IN_CH 128

// ---------------- scratch (device globals; no allocation) ----------------
__device__ float g_xW1[(size_t)NN * 64];
__device__ float g_alS1[(size_t)NN * 8];
__device__ float g_alD1[(size_t)NN * 8];
__device__ float g_h1[(size_t)NN * 64];
__device__ float g_xW2[(size_t)NN * 64];
__device__ float g_alS2[NN];
__device__ float g_alD2[NN];
__device__ float g_h2[(size_t)NN * 64];
__device__ float g_h3[(size_t)NN * 64];
__device__ float g_A[(size_t)NN * 128];
__device__ float g_B[(size_t)NN * 128];
__device__ int   g_deg[NN];
__device__ int   g_roff[NN + 4];
__device__ int   g_cur[NN];
__device__ int   g_csrc[NE];
__device__ int   g_binc[128];
__device__ int   g_bflag[128];

// ---------------- small node GEMM: Y[M,NC] = X[M,K] @ W[K,NC] (+bias) ----------------
// DUAL: blockIdx.y==1 uses (Wb, biasb, Yb) — fuses two independent GEMMs in one launch.
template<int K, int NC, int EPI, bool DUAL>
__global__ __launch_bounds__(256)
void node_gemm_kernel(const float* __restrict__ X,
                      const float* __restrict__ W,
                      const float* __restrict__ bias,
                      const float* __restrict__ aS,
                      const float* __restrict__ aD,
                      float* __restrict__ Y,
                      float* __restrict__ alS,
                      float* __restrict__ alD,
                      int n,
                      const float* __restrict__ Wb,
                      const float* __restrict__ biasb,
                      float* __restrict__ Yb)
{
    constexpr int BM = 128, BK = 32;
    constexpr int TNC = (NC == 64) ? 8 : 16;
    constexpr int TM = 4;
    __shared__ float Xs[BK][BM];
    __shared__ float Ws[BK][NC];

    const float* Wp = W;
    const float* biasp = bias;
    float* Yp = Y;
    if (DUAL && blockIdx.y == 1) { Wp = Wb; biasp = biasb; Yp = Yb; }

    const int t   = threadIdx.x;
    const int tc  = t & 7;
    const int tr  = t >> 3;
    const int row0 = blockIdx.x * BM;
    const bool has_bias = (biasp != nullptr);

    float acc[TM][TNC];
#pragma unroll
    for (int i = 0; i < TM; i++)
#pragma unroll
        for (int j = 0; j < TNC; j++) acc[i][j] = 0.0f;

    for (int k0 = 0; k0 < K; k0 += BK) {
        __syncthreads();
        for (int i = t; i < BM * BK / 4; i += 256) {
            int r = i >> 3;
            int kk = (i & 7) * 4;
            int grow = row0 + r;
            float4 v = make_float4(0.f, 0.f, 0.f, 0.f);
            if (grow < n) v = *(const float4*)(X + (size_t)grow * K + k0 + kk);
            Xs[kk + 0][r] = v.x; Xs[kk + 1][r] = v.y;
            Xs[kk + 2][r] = v.z; Xs[kk + 3][r] = v.w;
        }
        for (int i = t; i < BK * NC / 4; i += 256) {
            int r = i / (NC / 4);
            int c = (i % (NC / 4)) * 4;
            *(float4*)&Ws[r][c] = *(const float4*)(Wp + (size_t)(k0 + r) * NC + c);
        }
        __syncthreads();
#pragma unroll
        for (int k = 0; k < BK; k++) {
            float xv[TM];
#pragma unroll
            for (int i = 0; i < TM; i++) xv[i] = Xs[k][tr * TM + i];
#pragma unroll
            for (int j4 = 0; j4 < TNC; j4 += 4) {
                float4 w4 = *(const float4*)&Ws[k][tc * TNC + j4];
#pragma unroll
                for (int i = 0; i < TM; i++) {
                    acc[i][j4 + 0] += xv[i] * w4.x;
                    acc[i][j4 + 1] += xv[i] * w4.y;
                    acc[i][j4 + 2] += xv[i] * w4.z;
                    acc[i][j4 + 3] += xv[i] * w4.w;
                }
            }
        }
    }

#pragma unroll
    for (int i = 0; i < TM; i++) {
        int row = row0 + tr * TM + i;
        bool ok = (row < n);
        float outv[TNC];
#pragma unroll
        for (int j = 0; j < TNC; j++) {
            float v = acc[i][j];
            if (has_bias) v += biasp[tc * TNC + j];
            outv[j] = v;
        }
        if (ok) {
            float* yrow = Yp + (size_t)row * NC + tc * TNC;
#pragma unroll
            for (int j4 = 0; j4 < TNC; j4 += 4)
                *(float4*)(yrow + j4) = make_float4(outv[j4], outv[j4 + 1], outv[j4 + 2], outv[j4 + 3]);
        }
        if constexpr (EPI == 1) {
            float pS = 0.f, pD = 0.f;
#pragma unroll
            for (int j = 0; j < TNC; j++) {
                pS += acc[i][j] * aS[tc * 8 + j];
                pD += acc[i][j] * aD[tc * 8 + j];
            }
            if (ok) {
                alS[(size_t)row * 8 + tc] = pS;
                alD[(size_t)row * 8 + tc] = pD;
            }
        }
        if constexpr (EPI == 2) {
            float pS = 0.f, pD = 0.f;
#pragma unroll
            for (int j = 0; j < TNC; j++) {
                pS += acc[i][j] * aS[tc * 8 + j];
                pD += acc[i][j] * aD[tc * 8 + j];
            }
#pragma unroll
            for (int d = 4; d; d >>= 1) {
                pS += __shfl_down_sync(0xffffffffu, pS, d);
                pD += __shfl_down_sync(0xffffffffu, pD, d);
            }
            if (ok && tc == 0) {
                alS[row] = pS;
                alD[row] = pD;
            }
        }
    }
}

// ---------------- CSR build ----------------
__global__ void zero_kernel(int* __restrict__ deg, int* __restrict__ flags, int n, int nb)
{
    int i = blockIdx.x * blockDim.x + threadIdx.x;
    if (i < n) deg[i] = 0;
    if (i < nb) flags[i] = 0;
}

__global__ void hist_kernel(const int* __restrict__ ei, int* __restrict__ deg, int E)
{
    int e = blockIdx.x * blockDim.x + threadIdx.x;
    if (e < E) atomicAdd(&deg[ei[E + e]], 1);   // dst
}

// Single-kernel chained exclusive scan. Grid = ceil(n/1024) = 98 blocks,
// all simultaneously resident on 148 SMs -> block b safely spins on b-1's flag.
__global__ __launch_bounds__(256)
void scan_chain_kernel(const int* __restrict__ deg,
                       int* __restrict__ roff, int* __restrict__ cur, int n,
                       volatile int* binc, volatile int* bflag)
{
    __shared__ int wexc[8];
    __shared__ int s_off;
    int b = blockIdx.x, t = threadIdx.x, lane = t & 31, wid = t >> 5;
    int base = b * 1024 + t * 4;

    int4 v = make_int4(0, 0, 0, 0);
    if (base + 3 < n) v = *(const int4*)(deg + base);
    else {
        if (base     < n) v.x = deg[base];
        if (base + 1 < n) v.y = deg[base + 1];
        if (base + 2 < n) v.z = deg[base + 2];
        if (base + 3 < n) v.w = deg[base + 3];
    }
    int tsum = v.x + v.y + v.z + v.w;
    int incl = tsum;
#pragma unroll
    for (int d = 1; d < 32; d <<= 1) {
        int u = __shfl_up_sync(0xffffffffu, incl, d);
        if (lane >= d) incl += u;
    }
    if (lane == 31) wexc[wid] = incl;
    __syncthreads();
    if (t == 0) {
        int a = 0;
#pragma unroll
        for (int i = 0; i < 8; i++) { int w = wexc[i]; wexc[i] = a; a += w; }
        int off = 0;
        if (b > 0) {
            while (bflag[b - 1] == 0) {}
            off = binc[b - 1];
        }
        binc[b] = off + a;
        __threadfence();
        bflag[b] = 1;
        s_off = off;
        if (b == gridDim.x - 1) roff[n] = off + a;
    }
    __syncthreads();
    int off = s_off + wexc[wid] + (incl - tsum);
    int p0 = off, p1 = off + v.x, p2 = p1 + v.y, p3 = p2 + v.z;
    if (base + 3 < n) {
        *(int4*)(roff + base) = make_int4(p0, p1, p2, p3);
        *(int4*)(cur  + base) = make_int4(p0, p1, p2, p3);
    } else {
        if (base     < n) { roff[base]     = p0; cur[base]     = p0; }
        if (base + 1 < n) { roff[base + 1] = p1; cur[base + 1] = p1; }
        if (base + 2 < n) { roff[base + 2] = p2; cur[base + 2] = p2; }
    }
}

__global__ void scatter_kernel(const int* __restrict__ ei, int* __restrict__ cur,
                               int* __restrict__ csrc, int E)
{
    int e = blockIdx.x * blockDim.x + threadIdx.x;
    if (e < E) {
        int d = ei[E + e];
        int p = atomicAdd(&cur[d], 1);
        csrc[p] = ei[e];
    }
}

// ---------------- GAT aggregation (warp per destination node) ----------------
// Chunk-prefetch csrc via warp-wide loads + shuffle to break the dependent-load chain.
template<int HEADS>
__global__ __launch_bounds__(256)
void gat_agg_kernel(const float* __restrict__ xW,
                    const float* __restrict__ alS,
                    const float* __restrict__ alD,
                    const int* __restrict__ roff,
                    const int* __restrict__ csrc,
                    const float* __restrict__ bias,
                    float* __restrict__ out, int n)
{
    int warp = (blockIdx.x * blockDim.x + threadIdx.x) >> 5;
    if (warp >= n) return;
    int l = threadIdx.x & 31;
    int i = warp;
    int h = (HEADS == 8) ? (l >> 2) : 0;
    float ald = alD[(size_t)i * HEADS + h];
    float accx = 0.f, accy = 0.f, ws = 0.f;
    int e0 = roff[i], e1 = roff[i + 1];
    for (int j = e0; j < e1; j += 32) {
        int cnt = min(32, e1 - j);
        int sreg = (l < cnt) ? csrc[j + l] : 0;
#pragma unroll 4
        for (int k = 0; k < cnt; k++) {
            int s = __shfl_sync(0xffffffffu, sreg, k);
            float e = alS[(size_t)s * HEADS + h] + ald;
            float w = __expf(fmaxf(e, 0.2f * e));
            float2 v = *(const float2*)(xW + (size_t)s * 64 + 2 * l);
            accx += w * v.x; accy += w * v.y; ws += w;
        }
    }
    {   // self loop
        float e = alS[(size_t)i * HEADS + h] + ald;
        float w = __expf(fmaxf(e, 0.2f * e));
        float2 v = *(const float2*)(xW + (size_t)i * 64 + 2 * l);
        accx += w * v.x; accy += w * v.y; ws += w;
    }
    float inv = 1.0f / ws;
    float o0 = accx * inv + bias[2 * l];
    float o1 = accy * inv + bias[2 * l + 1];
    o0 = (o0 > 0.f) ? o0 : (__expf(o0) - 1.0f);
    o1 = (o1 > 0.f) ? o1 : (__expf(o1) - 1.0f);
    float2* orow = (float2*)(out + (size_t)i * 64 + 2 * l);
    *orow = make_float2(o0, o1);
}

// ---------------- edge MLP (warp per edge) ----------------
__global__ __launch_bounds__(256)
void edge_mlp_kernel(const int* __restrict__ ei,
                     const float* __restrict__ eattr,
                     const float* __restrict__ A,
                     const float* __restrict__ B,
                     const float* __restrict__ W1c,  // [16][128]
                     const float* __restrict__ W2,   // [128][2]
                     const float* __restrict__ b2,
                     float* __restrict__ out, int E)
{
    __shared__ float  Wc[16][128];
    __shared__ float2 W2s[128];
    __shared__ float  b2s[2];
    int t = threadIdx.x;
    for (int i = t; i < 16 * 128; i += 256) Wc[i >> 7][i & 127] = W1c[i];
    for (int i = t; i < 128; i += 256) W2s[i] = make_float2(W2[i * 2], W2[i * 2 + 1]);
    if (t < 2) b2s[t] = b2[t];
    __syncthreads();

    int e = (int)((blockIdx.x * 256 + t) >> 5);
    if (e >= E) return;
    int l = t & 31;
    int src = ei[e];
    int dst = ei[E + e];

    float4 a4 = *(const float4*)(A + (size_t)src * 128 + 4 * l);
    float4 b4 = *(const float4*)(B + (size_t)dst * 128 + 4 * l);
    float p0 = a4.x + b4.x, p1 = a4.y + b4.y, p2 = a4.z + b4.z, p3 = a4.w + b4.w;

    float eav = (l < 16) ? eattr[(size_t)e * 16 + l] : 0.f;
#pragma unroll
    for (int k = 0; k < 16; k++) {
        float ek = __shfl_sync(0xffffffffu, eav, k);
        float4 w4 = *(const float4*)&Wc[k][4 * l];
        p0 += ek * w4.x; p1 += ek * w4.y; p2 += ek * w4.z; p3 += ek * w4.w;
    }
    p0 = fmaxf(p0, 0.f); p1 = fmaxf(p1, 0.f); p2 = fmaxf(p2, 0.f); p3 = fmaxf(p3, 0.f);

    float2 c0 = W2s[4 * l + 0], c1 = W2s[4 * l + 1], c2 = W2s[4 * l + 2], c3 = W2s[4 * l + 3];
    float s0 = p0 * c0.x + p1 * c1.x + p2 * c2.x + p3 * c3.x;
    float s1 = p0 * c0.y + p1 * c1.y + p2 * c2.y + p3 * c3.y;
#pragma unroll
    for (int d = 16; d; d >>= 1) {
        s0 += __shfl_xor_sync(0xffffffffu, s0, d);
        s1 += __shfl_xor_sync(0xffffffffu, s1, d);
    }
    if (l == 0) {
        float eo0 = s0 + b2s[0];
        float eo1 = s1 + b2s[1];
        float m = fmaxf(eo0, eo1);
        float lse = m + log1pf(__expf(fminf(eo0, eo1) - m));
        float2* op = (float2*)(out + (size_t)e * 2);
        *op = make_float2(eo0 - lse, eo1 - lse);
    }
}

// ---------------- launcher (pure stream-0: maximally capture-safe) ----------------
extern "C" void kernel_launch(void* const* d_in, const int* in_sizes, int n_in,
                              void* d_out, int out_size)
{
    const float* x        = (const float*)d_in[0];
    const int*   ei       = (const int*)  d_in[1];
    const float* eattr    = (const float*)d_in[2];
    const float* W1       = (const float*)d_in[3];
    const float* a_src1   = (const float*)d_in[4];
    const float* a_dst1   = (const float*)d_in[5];
    const float* b1       = (const float*)d_in[6];
    const float* W2       = (const float*)d_in[7];
    const float* a_src2   = (const float*)d_in[8];
    const float* a_dst2   = (const float*)d_in[9];
    const float* b2       = (const float*)d_in[10];
    const float* lin_W    = (const float*)d_in[11];
    const float* lin_b    = (const float*)d_in[12];
    const float* mlp_W1   = (const float*)d_in[13];
    const float* mlp_b1   = (const float*)d_in[14];
    const float* mlp_W2   = (const float*)d_in[15];
    const float* mlp_b2   = (const float*)d_in[16];
    float* outp = (float*)d_out;

    const int n = in_sizes[0] / IN_CH;       // 100000
    const int E = in_sizes[1] / 2;           // 1600000

    float *p_xW1, *p_alS1, *p_alD1, *p_h1, *p_xW2, *p_alS2, *p_alD2, *p_h2, *p_h3, *p_A, *p_B;
    int *p_deg, *p_roff, *p_cur, *p_csrc, *p_binc, *p_bflag;
    cudaGetSymbolAddress((void**)&p_xW1,  g_xW1);
    cudaGetSymbolAddress((void**)&p_alS1, g_alS1);
    cudaGetSymbolAddress((void**)&p_alD1, g_alD1);
    cudaGetSymbolAddress((void**)&p_h1,   g_h1);
    cudaGetSymbolAddress((void**)&p_xW2,  g_xW2);
    cudaGetSymbolAddress((void**)&p_alS2, g_alS2);
    cudaGetSymbolAddress((void**)&p_alD2, g_alD2);
    cudaGetSymbolAddress((void**)&p_h2,   g_h2);
    cudaGetSymbolAddress((void**)&p_h3,   g_h3);
    cudaGetSymbolAddress((void**)&p_A,    g_A);
    cudaGetSymbolAddress((void**)&p_B,    g_B);
    cudaGetSymbolAddress((void**)&p_deg,  g_deg);
    cudaGetSymbolAddress((void**)&p_roff, g_roff);
    cudaGetSymbolAddress((void**)&p_cur,  g_cur);
    cudaGetSymbolAddress((void**)&p_csrc, g_csrc);
    cudaGetSymbolAddress((void**)&p_binc, g_binc);
    cudaGetSymbolAddress((void**)&p_bflag,g_bflag);

    const int gemm_blocks = (n + 127) / 128;
    const int agg_blocks  = (n * 32 + 255) / 256;
    const int e_blocks    = (E + 255) / 256;
    const int mlp_blocks  = (int)(((size_t)E * 32 + 255) / 256);
    const int scan_blocks = (n + 1023) / 1024;

    // launch #1: GEMM1 (xW1 = x@W1, per-head attention logits)
    node_gemm_kernel<128, 64, 1, false><<<gemm_blocks, 256>>>(
        x, W1, nullptr, a_src1, a_dst1, p_xW1, p_alS1, p_alD1, n,
        nullptr, nullptr, nullptr);

    // launches #2-#5: CSR build chain
    zero_kernel<<<(n + 255) / 256, 256>>>(p_deg, p_bflag, n, scan_blocks);
    hist_kernel<<<e_blocks, 256>>>(ei, p_deg, E);
    scan_chain_kernel<<<scan_blocks, 256>>>(p_deg, p_roff, p_cur, n, p_binc, p_bflag);
    scatter_kernel<<<e_blocks, 256>>>(ei, p_cur, p_csrc, E);

    // launch #6: GAT layer 1 aggregation (ncu capture target at -s 5)
    gat_agg_kernel<8><<<agg_blocks, 256>>>(p_xW1, p_alS1, p_alD1, p_roff, p_csrc, b1, p_h1, n);

    // launch #7: GEMM2
    node_gemm_kernel<64, 64, 2, false><<<gemm_blocks, 256>>>(
        p_h1, W2, nullptr, a_src2, a_dst2, p_xW2, p_alS2, p_alD2, n,
        nullptr, nullptr, nullptr);

    // launch #8: GAT layer 2 aggregation
    gat_agg_kernel<1><<<agg_blocks, 256>>>(p_xW2, p_alS2, p_alD2, p_roff, p_csrc, b2, p_h2, n);

    // launch #9: h3 = h2 @ lin_W + lin_b
    node_gemm_kernel<64, 64, 0, false><<<gemm_blocks, 256>>>(
        p_h2, lin_W, lin_b, nullptr, nullptr, p_h3, nullptr, nullptr, n,
        nullptr, nullptr, nullptr);

    // launch #10: fused A and B GEMMs in a single launch (gridDim.y = 2)
    //   y==0: A = h3 @ mlp_W1[0:64]  + mlp_b1
    //   y==1: B = h3 @ mlp_W1[64:128]
    node_gemm_kernel<64, 128, 0, true><<<dim3(gemm_blocks, 2), 256>>>(
        p_h3, mlp_W1, mlp_b1, nullptr, nullptr, p_A, nullptr, nullptr, n,
        mlp_W1 + (size_t)64 * 128, nullptr, p_B);

    // launch #11: edge MLP + log_softmax (Wc = mlp_W1 rows 128..143)
    edge_mlp_kernel<<<mlp_blocks, 256>>>(
        ei, eattr, p_A, p_B, mlp_W1 + (size_t)128 * 128, mlp_W2, mlp_b2, outp, E);
}

// round 13
// speedup vs baseline: 1.0878x; 1.0878x over previous
#include <cuda_runtime.h>
#include <math.h>

// ---------------- problem constants ----------------
#define NN 100000
#define NE 1600000
#define IN_CH 128

// ---------------- scratch (device globals; no allocation) ----------------
__device__ float g_xW1[(size_t)NN * 64];
__device__ float g_alS1[(size_t)NN * 8];
__device__ float g_alD1[(size_t)NN * 8];
__device__ float g_h1[(size_t)NN * 64];
__device__ float g_xW2[(size_t)NN * 64];
__device__ float g_alS2[NN];
__device__ float g_alD2[NN];
__device__ float g_h2[(size_t)NN * 64];
__device__ float g_h3[(size_t)NN * 64];
__device__ float g_A[(size_t)NN * 128];
__device__ float g_B[(size_t)NN * 128];
__device__ int   g_deg[NN];
__device__ int   g_roff[NN + 4];
__device__ int   g_cur[NN];
__device__ int   g_csrc[NE];
__device__ int   g_bsum[128];

// ---------------- small node GEMM: Y[M,NC] = X[M,K] @ W[K,NC] (+bias) ----------------
// DUAL: blockIdx.y==1 uses (Wb, biasb, Yb) — fuses two independent GEMMs in one launch.
template<int K, int NC, int EPI, bool DUAL>
__global__ __launch_bounds__(256)
void node_gemm_kernel(const float* __restrict__ X,
                      const float* __restrict__ W,
                      const float* __restrict__ bias,
                      const float* __restrict__ aS,
                      const float* __restrict__ aD,
                      float* __restrict__ Y,
                      float* __restrict__ alS,
                      float* __restrict__ alD,
                      int n,
                      const float* __restrict__ Wb,
                      const float* __restrict__ biasb,
                      float* __restrict__ Yb)
{
    constexpr int BM = 128, BK = 32;
    constexpr int TNC = (NC == 64) ? 8 : 16;
    constexpr int TM = 4;
    __shared__ float Xs[BK][BM];
    __shared__ float Ws[BK][NC];

    const float* Wp = W;
    const float* biasp = bias;
    float* Yp = Y;
    if (DUAL && blockIdx.y == 1) { Wp = Wb; biasp = biasb; Yp = Yb; }

    const int t   = threadIdx.x;
    const int tc  = t & 7;
    const int tr  = t >> 3;
    const int row0 = blockIdx.x * BM;
    const bool has_bias = (biasp != nullptr);

    float acc[TM][TNC];
#pragma unroll
    for (int i = 0; i < TM; i++)
#pragma unroll
        for (int j = 0; j < TNC; j++) acc[i][j] = 0.0f;

    for (int k0 = 0; k0 < K; k0 += BK) {
        __syncthreads();
        for (int i = t; i < BM * BK / 4; i += 256) {
            int r = i >> 3;
            int kk = (i & 7) * 4;
            int grow = row0 + r;
            float4 v = make_float4(0.f, 0.f, 0.f, 0.f);
            if (grow < n) v = *(const float4*)(X + (size_t)grow * K + k0 + kk);
            Xs[kk + 0][r] = v.x; Xs[kk + 1][r] = v.y;
            Xs[kk + 2][r] = v.z; Xs[kk + 3][r] = v.w;
        }
        for (int i = t; i < BK * NC / 4; i += 256) {
            int r = i / (NC / 4);
            int c = (i % (NC / 4)) * 4;
            *(float4*)&Ws[r][c] = *(const float4*)(Wp + (size_t)(k0 + r) * NC + c);
        }
        __syncthreads();
#pragma unroll
        for (int k = 0; k < BK; k++) {
            float xv[TM];
#pragma unroll
            for (int i = 0; i < TM; i++) xv[i] = Xs[k][tr * TM + i];
#pragma unroll
            for (int j4 = 0; j4 < TNC; j4 += 4) {
                float4 w4 = *(const float4*)&Ws[k][tc * TNC + j4];
#pragma unroll
                for (int i = 0; i < TM; i++) {
                    acc[i][j4 + 0] += xv[i] * w4.x;
                    acc[i][j4 + 1] += xv[i] * w4.y;
                    acc[i][j4 + 2] += xv[i] * w4.z;
                    acc[i][j4 + 3] += xv[i] * w4.w;
                }
            }
        }
    }

#pragma unroll
    for (int i = 0; i < TM; i++) {
        int row = row0 + tr * TM + i;
        bool ok = (row < n);
        float outv[TNC];
#pragma unroll
        for (int j = 0; j < TNC; j++) {
            float v = acc[i][j];
            if (has_bias) v += biasp[tc * TNC + j];
            outv[j] = v;
        }
        if (ok) {
            float* yrow = Yp + (size_t)row * NC + tc * TNC;
#pragma unroll
            for (int j4 = 0; j4 < TNC; j4 += 4)
                *(float4*)(yrow + j4) = make_float4(outv[j4], outv[j4 + 1], outv[j4 + 2], outv[j4 + 3]);
        }
        if constexpr (EPI == 1) {
            float pS = 0.f, pD = 0.f;
#pragma unroll
            for (int j = 0; j < TNC; j++) {
                pS += acc[i][j] * aS[tc * 8 + j];
                pD += acc[i][j] * aD[tc * 8 + j];
            }
            if (ok) {
                alS[(size_t)row * 8 + tc] = pS;
                alD[(size_t)row * 8 + tc] = pD;
            }
        }
        if constexpr (EPI == 2) {
            float pS = 0.f, pD = 0.f;
#pragma unroll
            for (int j = 0; j < TNC; j++) {
                pS += acc[i][j] * aS[tc * 8 + j];
                pD += acc[i][j] * aD[tc * 8 + j];
            }
#pragma unroll
            for (int d = 4; d; d >>= 1) {
                pS += __shfl_down_sync(0xffffffffu, pS, d);
                pD += __shfl_down_sync(0xffffffffu, pD, d);
            }
            if (ok && tc == 0) {
                alS[row] = pS;
                alD[row] = pD;
            }
        }
    }
}

// ---------------- CSR build ----------------
__global__ void zero_kernel(int* __restrict__ deg, int n)
{
    int i = blockIdx.x * blockDim.x + threadIdx.x;
    if (i < n) deg[i] = 0;
}

__global__ void hist_kernel(const int* __restrict__ ei, int* __restrict__ deg, int E)
{
    int e = blockIdx.x * blockDim.x + threadIdx.x;
    if (e < E) atomicAdd(&deg[ei[E + e]], 1);   // dst
}

// Two-pass parallel scan: NO inter-block dependences (the R7 flag-chain cost
// ~1us per hop x 98 hops = 97us; this replaces it with two ~6us parallel passes).
// pass1: block b sums deg[b*1024 .. b*1024+1023] -> bsum[b]
__global__ __launch_bounds__(256)
void scan_pass1_kernel(const int* __restrict__ deg, int* __restrict__ bsum, int n)
{
    __shared__ int wsum[8];
    int b = blockIdx.x, t = threadIdx.x, lane = t & 31, wid = t >> 5;
    int base = b * 1024 + t * 4;
    int4 v = make_int4(0, 0, 0, 0);
    if (base + 3 < n) v = *(const int4*)(deg + base);
    else {
        if (base     < n) v.x = deg[base];
        if (base + 1 < n) v.y = deg[base + 1];
        if (base + 2 < n) v.z = deg[base + 2];
        if (base + 3 < n) v.w = deg[base + 3];
    }
    int s = v.x + v.y + v.z + v.w;
#pragma unroll
    for (int d = 16; d; d >>= 1) s += __shfl_down_sync(0xffffffffu, s, d);
    if (lane == 0) wsum[wid] = s;
    __syncthreads();
    if (t == 0) {
        int a = 0;
#pragma unroll
        for (int i = 0; i < 8; i++) a += wsum[i];
        bsum[b] = a;
    }
}

// pass2: block b redundantly prefixes bsum[0..b-1] (98 ints in smem, trivial),
// then does its intra-block exclusive scan and writes roff/cur (+roff[n] by last block).
__global__ __launch_bounds__(256)
void scan_pass2_kernel(const int* __restrict__ deg, const int* __restrict__ bsum,
                       int* __restrict__ roff, int* __restrict__ cur, int n, int nb)
{
    __shared__ int sbs[128];
    __shared__ int wexc[8];
    __shared__ int s_off;
    int b = blockIdx.x, t = threadIdx.x, lane = t & 31, wid = t >> 5;

    if (t < 128) sbs[t] = (t < nb) ? bsum[t] : 0;

    int base = b * 1024 + t * 4;
    int4 v = make_int4(0, 0, 0, 0);
    if (base + 3 < n) v = *(const int4*)(deg + base);
    else {
        if (base     < n) v.x = deg[base];
        if (base + 1 < n) v.y = deg[base + 1];
        if (base + 2 < n) v.z = deg[base + 2];
        if (base + 3 < n) v.w = deg[base + 3];
    }
    int tsum = v.x + v.y + v.z + v.w;
    int incl = tsum;
#pragma unroll
    for (int d = 1; d < 32; d <<= 1) {
        int u = __shfl_up_sync(0xffffffffu, incl, d);
        if (lane >= d) incl += u;
    }
    if (lane == 31) wexc[wid] = incl;
    __syncthreads();
    if (t == 0) {
        int a = 0;
#pragma unroll
        for (int i = 0; i < 8; i++) { int w = wexc[i]; wexc[i] = a; a += w; }
        int off = 0;
        for (int i = 0; i < b; i++) off += sbs[i];
        s_off = off;
        if (b == nb - 1) {
            int tot = off;
            for (int i = b; i < nb; i++) tot += sbs[i];
            roff[n] = tot;
        }
    }
    __syncthreads();
    int off = s_off + wexc[wid] + (incl - tsum);
    int p0 = off, p1 = off + v.x, p2 = p1 + v.y, p3 = p2 + v.z;
    if (base + 3 < n) {
        *(int4*)(roff + base) = make_int4(p0, p1, p2, p3);
        *(int4*)(cur  + base) = make_int4(p0, p1, p2, p3);
    } else {
        if (base     < n) { roff[base]     = p0; cur[base]     = p0; }
        if (base + 1 < n) { roff[base + 1] = p1; cur[base + 1] = p1; }
        if (base + 2 < n) { roff[base + 2] = p2; cur[base + 2] = p2; }
    }
}

__global__ void scatter_kernel(const int* __restrict__ ei, int* __restrict__ cur,
                               int* __restrict__ csrc, int E)
{
    int e = blockIdx.x * blockDim.x + threadIdx.x;
    if (e < E) {
        int d = ei[E + e];
        int p = atomicAdd(&cur[d], 1);
        csrc[p] = ei[e];
    }
}

// ---------------- GAT aggregation (warp per destination node) ----------------
// Simple per-edge loop (this exact form measured in the 1400.6us run).
template<int HEADS>
__global__ __launch_bounds__(256)
void gat_agg_kernel(const float* __restrict__ xW,
                    const float* __restrict__ alS,
                    const float* __restrict__ alD,
                    const int* __restrict__ roff,
                    const int* __restrict__ csrc,
                    const float* __restrict__ bias,
                    float* __restrict__ out, int n)
{
    int warp = (blockIdx.x * blockDim.x + threadIdx.x) >> 5;
    if (warp >= n) return;
    int l = threadIdx.x & 31;
    int i = warp;
    int h = (HEADS == 8) ? (l >> 2) : 0;
    float ald = alD[(size_t)i * HEADS + h];
    float accx = 0.f, accy = 0.f, ws = 0.f;
    int e0 = roff[i], e1 = roff[i + 1];
    for (int j = e0; j < e1; j++) {
        int s = csrc[j];
        float e = alS[(size_t)s * HEADS + h] + ald;
        float w = __expf(fmaxf(e, 0.2f * e));
        float2 v = *(const float2*)(xW + (size_t)s * 64 + 2 * l);
        accx += w * v.x; accy += w * v.y; ws += w;
    }
    {   // self loop
        float e = alS[(size_t)i * HEADS + h] + ald;
        float w = __expf(fmaxf(e, 0.2f * e));
        float2 v = *(const float2*)(xW + (size_t)i * 64 + 2 * l);
        accx += w * v.x; accy += w * v.y; ws += w;
    }
    float inv = 1.0f / ws;
    float o0 = accx * inv + bias[2 * l];
    float o1 = accy * inv + bias[2 * l + 1];
    o0 = (o0 > 0.f) ? o0 : (__expf(o0) - 1.0f);
    o1 = (o1 > 0.f) ? o1 : (__expf(o1) - 1.0f);
    float2* orow = (float2*)(out + (size_t)i * 64 + 2 * l);
    *orow = make_float2(o0, o1);
}

// ---------------- edge MLP (warp per edge) ----------------
__global__ __launch_bounds__(256)
void edge_mlp_kernel(const int* __restrict__ ei,
                     const float* __restrict__ eattr,
                     const float* __restrict__ A,
                     const float* __restrict__ B,
                     const float* __restrict__ W1c,  // [16][128]
                     const float* __restrict__ W2,   // [128][2]
                     const float* __restrict__ b2,
                     float* __restrict__ out, int E)
{
    __shared__ float  Wc[16][128];
    __shared__ float2 W2s[128];
    __shared__ float  b2s[2];
    int t = threadIdx.x;
    for (int i = t; i < 16 * 128; i += 256) Wc[i >> 7][i & 127] = W1c[i];
    for (int i = t; i < 128; i += 256) W2s[i] = make_float2(W2[i * 2], W2[i * 2 + 1]);
    if (t < 2) b2s[t] = b2[t];
    __syncthreads();

    int e = (int)((blockIdx.x * 256 + t) >> 5);
    if (e >= E) return;
    int l = t & 31;
    int src = ei[e];
    int dst = ei[E + e];

    float4 a4 = *(const float4*)(A + (size_t)src * 128 + 4 * l);
    float4 b4 = *(const float4*)(B + (size_t)dst * 128 + 4 * l);
    float p0 = a4.x + b4.x, p1 = a4.y + b4.y, p2 = a4.z + b4.z, p3 = a4.w + b4.w;

    float eav = (l < 16) ? eattr[(size_t)e * 16 + l] : 0.f;
#pragma unroll
    for (int k = 0; k < 16; k++) {
        float ek = __shfl_sync(0xffffffffu, eav, k);
        float4 w4 = *(const float4*)&Wc[k][4 * l];
        p0 += ek * w4.x; p1 += ek * w4.y; p2 += ek * w4.z; p3 += ek * w4.w;
    }
    p0 = fmaxf(p0, 0.f); p1 = fmaxf(p1, 0.f); p2 = fmaxf(p2, 0.f); p3 = fmaxf(p3, 0.f);

    float2 c0 = W2s[4 * l + 0], c1 = W2s[4 * l + 1], c2 = W2s[4 * l + 2], c3 = W2s[4 * l + 3];
    float s0 = p0 * c0.x + p1 * c1.x + p2 * c2.x + p3 * c3.x;
    float s1 = p0 * c0.y + p1 * c1.y + p2 * c2.y + p3 * c3.y;
#pragma unroll
    for (int d = 16; d; d >>= 1) {
        s0 += __shfl_xor_sync(0xffffffffu, s0, d);
        s1 += __shfl_xor_sync(0xffffffffu, s1, d);
    }
    if (l == 0) {
        float eo0 = s0 + b2s[0];
        float eo1 = s1 + b2s[1];
        float m = fmaxf(eo0, eo1);
        float lse = m + log1pf(__expf(fminf(eo0, eo1) - m));
        float2* op = (float2*)(out + (size_t)e * 2);
        *op = make_float2(eo0 - lse, eo1 - lse);
    }
}

// ---------------- launcher (pure stream-0) ----------------
extern "C" void kernel_launch(void* const* d_in, const int* in_sizes, int n_in,
                              void* d_out, int out_size)
{
    const float* x        = (const float*)d_in[0];
    const int*   ei       = (const int*)  d_in[1];
    const float* eattr    = (const float*)d_in[2];
    const float* W1       = (const float*)d_in[3];
    const float* a_src1   = (const float*)d_in[4];
    const float* a_dst1   = (const float*)d_in[5];
    const float* b1       = (const float*)d_in[6];
    const float* W2       = (const float*)d_in[7];
    const float* a_src2   = (const float*)d_in[8];
    const float* a_dst2   = (const float*)d_in[9];
    const float* b2       = (const float*)d_in[10];
    const float* lin_W    = (const float*)d_in[11];
    const float* lin_b    = (const float*)d_in[12];
    const float* mlp_W1   = (const float*)d_in[13];
    const float* mlp_b1   = (const float*)d_in[14];
    const float* mlp_W2   = (const float*)d_in[15];
    const float* mlp_b2   = (const float*)d_in[16];
    float* outp = (float*)d_out;

    const int n = in_sizes[0] / IN_CH;       // 100000
    const int E = in_sizes[1] / 2;           // 1600000

    float *p_xW1, *p_alS1, *p_alD1, *p_h1, *p_xW2, *p_alS2, *p_alD2, *p_h2, *p_h3, *p_A, *p_B;
    int *p_deg, *p_roff, *p_cur, *p_csrc, *p_bsum;
    cudaGetSymbolAddress((void**)&p_xW1,  g_xW1);
    cudaGetSymbolAddress((void**)&p_alS1, g_alS1);
    cudaGetSymbolAddress((void**)&p_alD1, g_alD1);
    cudaGetSymbolAddress((void**)&p_h1,   g_h1);
    cudaGetSymbolAddress((void**)&p_xW2,  g_xW2);
    cudaGetSymbolAddress((void**)&p_alS2, g_alS2);
    cudaGetSymbolAddress((void**)&p_alD2, g_alD2);
    cudaGetSymbolAddress((void**)&p_h2,   g_h2);
    cudaGetSymbolAddress((void**)&p_h3,   g_h3);
    cudaGetSymbolAddress((void**)&p_A,    g_A);
    cudaGetSymbolAddress((void**)&p_B,    g_B);
    cudaGetSymbolAddress((void**)&p_deg,  g_deg);
    cudaGetSymbolAddress((void**)&p_roff, g_roff);
    cudaGetSymbolAddress((void**)&p_cur,  g_cur);
    cudaGetSymbolAddress((void**)&p_csrc, g_csrc);
    cudaGetSymbolAddress((void**)&p_bsum, g_bsum);

    const int gemm_blocks = (n + 127) / 128;
    const int agg_blocks  = (n * 32 + 255) / 256;
    const int e_blocks    = (E + 255) / 256;
    const int mlp_blocks  = (int)(((size_t)E * 32 + 255) / 256);
    const int scan_blocks = (n + 1023) / 1024;   // 98

    // launch #1: zero degree histogram
    zero_kernel<<<(n + 255) / 256, 256>>>(p_deg, n);

    // launch #2: degree histogram
    hist_kernel<<<e_blocks, 256>>>(ei, p_deg, E);

    // launch #3: scan pass 1 (block sums)
    scan_pass1_kernel<<<scan_blocks, 256>>>(p_deg, p_bsum, n);

    // launch #4: GEMM1 — CSR-independent, placed here so ncu's capture
    // (harness+our-#4 = overall #6 at -s 5) lands on it.
    node_gemm_kernel<128, 64, 1, false><<<gemm_blocks, 256>>>(
        x, W1, nullptr, a_src1, a_dst1, p_xW1, p_alS1, p_alD1, n,
        nullptr, nullptr, nullptr);

    // launch #5: scan pass 2 (roff/cur)
    scan_pass2_kernel<<<scan_blocks, 256>>>(p_deg, p_bsum, p_roff, p_cur, n, scan_blocks);

    // launch #6: scatter sources into CSR
    scatter_kernel<<<e_blocks, 256>>>(ei, p_cur, p_csrc, E);

    // launch #7: GAT layer 1 aggregation
    gat_agg_kernel<8><<<agg_blocks, 256>>>(p_xW1, p_alS1, p_alD1, p_roff, p_csrc, b1, p_h1, n);

    // launch #8: GEMM2
    node_gemm_kernel<64, 64, 2, false><<<gemm_blocks, 256>>>(
        p_h1, W2, nullptr, a_src2, a_dst2, p_xW2, p_alS2, p_alD2, n,
        nullptr, nullptr, nullptr);

    // launch #9: GAT layer 2 aggregation
    gat_agg_kernel<1><<<agg_blocks, 256>>>(p_xW2, p_alS2, p_alD2, p_roff, p_csrc, b2, p_h2, n);

    // launch #10: h3 = h2 @ lin_W + lin_b
    node_gemm_kernel<64, 64, 0, false><<<gemm_blocks, 256>>>(
        p_h2, lin_W, lin_b, nullptr, nullptr, p_h3, nullptr, nullptr, n,
        nullptr, nullptr, nullptr);

    // launch #11: fused A and B GEMMs (gridDim.y = 2)
    node_gemm_kernel<64, 128, 0, true><<<dim3(gemm_blocks, 2), 256>>>(
        p_h3, mlp_W1, mlp_b1, nullptr, nullptr, p_A, nullptr, nullptr, n,
        mlp_W1 + (size_t)64 * 128, nullptr, p_B);

    // launch #12: edge MLP + log_softmax (Wc = mlp_W1 rows 128..143)
    edge_mlp_kernel<<<mlp_blocks, 256>>>(
        ei, eattr, p_A, p_B, mlp_W1 + (size_t)128 * 128, mlp_W2, mlp_b2, outp, E);
}

// round 17
// speedup vs baseline: 1.2367x; 1.1369x over previous
#include <cuda_runtime.h>
#include <math.h>

// ---------------- problem constants ----------------
#define NN 100000
#define NE 1600000
#define IN_CH 128

// ---------------- scratch (device globals; no allocation) ----------------
__device__ float g_xW1[(size_t)NN * 64];
__device__ float g_alS1[(size_t)NN * 8];
__device__ float g_alD1[(size_t)NN * 8];
__device__ float g_h1[(size_t)NN * 64];
__device__ float g_xW2[(size_t)NN * 64];
__device__ float g_alS2[NN];
__device__ float g_alD2[NN];
__device__ float g_h2[(size_t)NN * 64];
__device__ float g_h3[(size_t)NN * 64];
__device__ float g_A[(size_t)NN * 128];
__device__ float g_B[(size_t)NN * 128];
__device__ int   g_deg[NN];
__device__ int   g_roff[NN + 4];
__device__ int   g_cur[NN];
__device__ int   g_csrc[NE];
__device__ int   g_bsum[128];

// ---------------- small node GEMM: Y[M,NC] = X[M,K] @ W[K,NC] (+bias) ----------------
// DUAL: blockIdx.y==1 uses (Wb, biasb, Yb).
// R13 ncu: L1/shared 75.7% (bound), fma 26.1% -> inner Xs loads were 4 scalar LDS;
// now one LDS.128 (16B-aligned, broadcast across 8 lanes, conflict-free).
template<int K, int NC, int EPI, bool DUAL>
__global__ __launch_bounds__(256)
void node_gemm_kernel(const float* __restrict__ X,
                      const float* __restrict__ W,
                      const float* __restrict__ bias,
                      const float* __restrict__ aS,
                      const float* __restrict__ aD,
                      float* __restrict__ Y,
                      float* __restrict__ alS,
                      float* __restrict__ alD,
                      int n,
                      const float* __restrict__ Wb,
                      const float* __restrict__ biasb,
                      float* __restrict__ Yb)
{
    constexpr int BM = 128, BK = 32;
    constexpr int TNC = (NC == 64) ? 8 : 16;
    constexpr int TM = 4;
    __shared__ float Xs[BK][BM];
    __shared__ float Ws[BK][NC];

    const float* Wp = W;
    const float* biasp = bias;
    float* Yp = Y;
    if (DUAL && blockIdx.y == 1) { Wp = Wb; biasp = biasb; Yp = Yb; }

    const int t   = threadIdx.x;
    const int tc  = t & 7;
    const int tr  = t >> 3;
    const int row0 = blockIdx.x * BM;
    const bool has_bias = (biasp != nullptr);

    float acc[TM][TNC];
#pragma unroll
    for (int i = 0; i < TM; i++)
#pragma unroll
        for (int j = 0; j < TNC; j++) acc[i][j] = 0.0f;

    for (int k0 = 0; k0 < K; k0 += BK) {
        __syncthreads();
        for (int i = t; i < BM * BK / 4; i += 256) {
            int r = i >> 3;
            int kk = (i & 7) * 4;
            int grow = row0 + r;
            float4 v = make_float4(0.f, 0.f, 0.f, 0.f);
            if (grow < n) v = *(const float4*)(X + (size_t)grow * K + k0 + kk);
            Xs[kk + 0][r] = v.x; Xs[kk + 1][r] = v.y;
            Xs[kk + 2][r] = v.z; Xs[kk + 3][r] = v.w;
        }
        for (int i = t; i < BK * NC / 4; i += 256) {
            int r = i / (NC / 4);
            int c = (i % (NC / 4)) * 4;
            *(float4*)&Ws[r][c] = *(const float4*)(Wp + (size_t)(k0 + r) * NC + c);
        }
        __syncthreads();
#pragma unroll
        for (int k = 0; k < BK; k++) {
            float4 xv4 = *(const float4*)&Xs[k][tr * TM];   // one LDS.128
            float xv[TM] = {xv4.x, xv4.y, xv4.z, xv4.w};
#pragma unroll
            for (int j4 = 0; j4 < TNC; j4 += 4) {
                float4 w4 = *(const float4*)&Ws[k][tc * TNC + j4];
#pragma unroll
                for (int i = 0; i < TM; i++) {
                    acc[i][j4 + 0] += xv[i] * w4.x;
                    acc[i][j4 + 1] += xv[i] * w4.y;
                    acc[i][j4 + 2] += xv[i] * w4.z;
                    acc[i][j4 + 3] += xv[i] * w4.w;
                }
            }
        }
    }

#pragma unroll
    for (int i = 0; i < TM; i++) {
        int row = row0 + tr * TM + i;
        bool ok = (row < n);
        float outv[TNC];
#pragma unroll
        for (int j = 0; j < TNC; j++) {
            float v = acc[i][j];
            if (has_bias) v += biasp[tc * TNC + j];
            outv[j] = v;
        }
        if (ok) {
            float* yrow = Yp + (size_t)row * NC + tc * TNC;
#pragma unroll
            for (int j4 = 0; j4 < TNC; j4 += 4)
                *(float4*)(yrow + j4) = make_float4(outv[j4], outv[j4 + 1], outv[j4 + 2], outv[j4 + 3]);
        }
        if constexpr (EPI == 1) {
            float pS = 0.f, pD = 0.f;
#pragma unroll
            for (int j = 0; j < TNC; j++) {
                pS += acc[i][j] * aS[tc * 8 + j];
                pD += acc[i][j] * aD[tc * 8 + j];
            }
            if (ok) {
                alS[(size_t)row * 8 + tc] = pS;
                alD[(size_t)row * 8 + tc] = pD;
            }
        }
        if constexpr (EPI == 2) {
            float pS = 0.f, pD = 0.f;
#pragma unroll
            for (int j = 0; j < TNC; j++) {
                pS += acc[i][j] * aS[tc * 8 + j];
                pD += acc[i][j] * aD[tc * 8 + j];
            }
#pragma unroll
            for (int d = 4; d; d >>= 1) {
                pS += __shfl_down_sync(0xffffffffu, pS, d);
                pD += __shfl_down_sync(0xffffffffu, pD, d);
            }
            if (ok && tc == 0) {
                alS[row] = pS;
                alD[row] = pD;
            }
        }
    }
}

// ---------------- CSR build ----------------
__global__ void zero_kernel(int* __restrict__ deg, int n)
{
    int i = blockIdx.x * blockDim.x + threadIdx.x;
    if (i < n) deg[i] = 0;
}

__global__ void hist_kernel(const int* __restrict__ ei, int* __restrict__ deg, int E)
{
    int e = blockIdx.x * blockDim.x + threadIdx.x;
    if (e < E) atomicAdd(&deg[ei[E + e]], 1);   // dst
}

// Two-pass parallel scan (measured win in R13: replaced 97us flag-chain).
__global__ __launch_bounds__(256)
void scan_pass1_kernel(const int* __restrict__ deg, int* __restrict__ bsum, int n)
{
    __shared__ int wsum[8];
    int b = blockIdx.x, t = threadIdx.x, lane = t & 31, wid = t >> 5;
    int base = b * 1024 + t * 4;
    int4 v = make_int4(0, 0, 0, 0);
    if (base + 3 < n) v = *(const int4*)(deg + base);
    else {
        if (base     < n) v.x = deg[base];
        if (base + 1 < n) v.y = deg[base + 1];
        if (base + 2 < n) v.z = deg[base + 2];
        if (base + 3 < n) v.w = deg[base + 3];
    }
    int s = v.x + v.y + v.z + v.w;
#pragma unroll
    for (int d = 16; d; d >>= 1) s += __shfl_down_sync(0xffffffffu, s, d);
    if (lane == 0) wsum[wid] = s;
    __syncthreads();
    if (t == 0) {
        int a = 0;
#pragma unroll
        for (int i = 0; i < 8; i++) a += wsum[i];
        bsum[b] = a;
    }
}

__global__ __launch_bounds__(256)
void scan_pass2_kernel(const int* __restrict__ deg, const int* __restrict__ bsum,
                       int* __restrict__ roff, int* __restrict__ cur, int n, int nb)
{
    __shared__ int sbs[128];
    __shared__ int wexc[8];
    __shared__ int s_off;
    int b = blockIdx.x, t = threadIdx.x, lane = t & 31, wid = t >> 5;

    if (t < 128) sbs[t] = (t < nb) ? bsum[t] : 0;

    int base = b * 1024 + t * 4;
    int4 v = make_int4(0, 0, 0, 0);
    if (base + 3 < n) v = *(const int4*)(deg + base);
    else {
        if (base     < n) v.x = deg[base];
        if (base + 1 < n) v.y = deg[base + 1];
        if (base + 2 < n) v.z = deg[base + 2];
        if (base + 3 < n) v.w = deg[base + 3];
    }
    int tsum = v.x + v.y + v.z + v.w;
    int incl = tsum;
#pragma unroll
    for (int d = 1; d < 32; d <<= 1) {
        int u = __shfl_up_sync(0xffffffffu, incl, d);
        if (lane >= d) incl += u;
    }
    if (lane == 31) wexc[wid] = incl;
    __syncthreads();
    if (t == 0) {
        int a = 0;
#pragma unroll
        for (int i = 0; i < 8; i++) { int w = wexc[i]; wexc[i] = a; a += w; }
        int off = 0;
        for (int i = 0; i < b; i++) off += sbs[i];
        s_off = off;
        if (b == nb - 1) {
            int tot = off;
            for (int i = b; i < nb; i++) tot += sbs[i];
            roff[n] = tot;
        }
    }
    __syncthreads();
    int off = s_off + wexc[wid] + (incl - tsum);
    int p0 = off, p1 = off + v.x, p2 = p1 + v.y, p3 = p2 + v.z;
    if (base + 3 < n) {
        *(int4*)(roff + base) = make_int4(p0, p1, p2, p3);
        *(int4*)(cur  + base) = make_int4(p0, p1, p2, p3);
    } else {
        if (base     < n) { roff[base]     = p0; cur[base]     = p0; }
        if (base + 1 < n) { roff[base + 1] = p1; cur[base + 1] = p1; }
        if (base + 2 < n) { roff[base + 2] = p2; cur[base + 2] = p2; }
    }
}

__global__ void scatter_kernel(const int* __restrict__ ei, int* __restrict__ cur,
                               int* __restrict__ csrc, int E)
{
    int e = blockIdx.x * blockDim.x + threadIdx.x;
    if (e < E) {
        int d = ei[E + e];
        int p = atomicAdd(&cur[d], 1);
        csrc[p] = ei[e];
    }
}

// ---------------- GAT aggregation (warp per destination node) ----------------
template<int HEADS>
__global__ __launch_bounds__(256)
void gat_agg_kernel(const float* __restrict__ xW,
                    const float* __restrict__ alS,
                    const float* __restrict__ alD,
                    const int* __restrict__ roff,
                    const int* __restrict__ csrc,
                    const float* __restrict__ bias,
                    float* __restrict__ out, int n)
{
    int warp = (blockIdx.x * blockDim.x + threadIdx.x) >> 5;
    if (warp >= n) return;
    int l = threadIdx.x & 31;
    int i = warp;
    int h = (HEADS == 8) ? (l >> 2) : 0;
    float ald = alD[(size_t)i * HEADS + h];
    float accx = 0.f, accy = 0.f, ws = 0.f;
    int e0 = roff[i], e1 = roff[i + 1];
    for (int j = e0; j < e1; j++) {
        int s = csrc[j];
        float e = alS[(size_t)s * HEADS + h] + ald;
        float w = __expf(fmaxf(e, 0.2f * e));
        float2 v = *(const float2*)(xW + (size_t)s * 64 + 2 * l);
        accx += w * v.x; accy += w * v.y; ws += w;
    }
    {   // self loop
        float e = alS[(size_t)i * HEADS + h] + ald;
        float w = __expf(fmaxf(e, 0.2f * e));
        float2 v = *(const float2*)(xW + (size_t)i * 64 + 2 * l);
        accx += w * v.x; accy += w * v.y; ws += w;
    }
    float inv = 1.0f / ws;
    float o0 = accx * inv + bias[2 * l];
    float o1 = accy * inv + bias[2 * l + 1];
    o0 = (o0 > 0.f) ? o0 : (__expf(o0) - 1.0f);
    o1 = (o1 > 0.f) ? o1 : (__expf(o1) - 1.0f);
    float2* orow = (float2*)(out + (size_t)i * 64 + 2 * l);
    *orow = make_float2(o0, o1);
}

// ---------------- edge MLP (grid-stride warp per edge) ----------------
// R13 fix: previously 200k blocks each staged 9KB of weights from global
// (~1.8GB redundant traffic). Now a fixed grid amortizes staging over ~100
// edges per warp; iterations are independent -> load overlap.
__global__ __launch_bounds__(256)
void edge_mlp_kernel(const int* __restrict__ ei,
                     const float* __restrict__ eattr,
                     const float* __restrict__ A,
                     const float* __restrict__ B,
                     const float* __restrict__ W1c,  // [16][128]
                     const float* __restrict__ W2,   // [128][2]
                     const float* __restrict__ b2,
                     float* __restrict__ out, int E)
{
    __shared__ float  Wc[16][128];
    __shared__ float2 W2s[128];
    __shared__ float  b2s[2];
    int t = threadIdx.x;
    for (int i = t; i < 16 * 128; i += 256) Wc[i >> 7][i & 127] = W1c[i];
    for (int i = t; i < 128; i += 256) W2s[i] = make_float2(W2[i * 2], W2[i * 2 + 1]);
    if (t < 2) b2s[t] = b2[t];
    __syncthreads();

    int l = t & 31;
    int warp0  = (int)((blockIdx.x * 256 + t) >> 5);
    int nwarps = (int)((gridDim.x * 256) >> 5);

    float2 c0 = W2s[4 * l + 0], c1 = W2s[4 * l + 1], c2 = W2s[4 * l + 2], c3 = W2s[4 * l + 3];

    for (int e = warp0; e < E; e += nwarps) {
        int src = ei[e];
        int dst = ei[E + e];

        float4 a4 = *(const float4*)(A + (size_t)src * 128 + 4 * l);
        float4 b4 = *(const float4*)(B + (size_t)dst * 128 + 4 * l);
        float p0 = a4.x + b4.x, p1 = a4.y + b4.y, p2 = a4.z + b4.z, p3 = a4.w + b4.w;

        float eav = (l < 16) ? eattr[(size_t)e * 16 + l] : 0.f;
#pragma unroll
        for (int k = 0; k < 16; k++) {
            float ek = __shfl_sync(0xffffffffu, eav, k);
            float4 w4 = *(const float4*)&Wc[k][4 * l];
            p0 += ek * w4.x; p1 += ek * w4.y; p2 += ek * w4.z; p3 += ek * w4.w;
        }
        p0 = fmaxf(p0, 0.f); p1 = fmaxf(p1, 0.f); p2 = fmaxf(p2, 0.f); p3 = fmaxf(p3, 0.f);

        float s0 = p0 * c0.x + p1 * c1.x + p2 * c2.x + p3 * c3.x;
        float s1 = p0 * c0.y + p1 * c1.y + p2 * c2.y + p3 * c3.y;
#pragma unroll
        for (int d = 16; d; d >>= 1) {
            s0 += __shfl_xor_sync(0xffffffffu, s0, d);
            s1 += __shfl_xor_sync(0xffffffffu, s1, d);
        }
        if (l == 0) {
            float eo0 = s0 + b2s[0];
            float eo1 = s1 + b2s[1];
            float m = fmaxf(eo0, eo1);
            float lse = m + log1pf(__expf(fminf(eo0, eo1) - m));
            float2* op = (float2*)(out + (size_t)e * 2);
            *op = make_float2(eo0 - lse, eo1 - lse);
        }
    }
}

// ---------------- launcher (pure stream-0) ----------------
extern "C" void kernel_launch(void* const* d_in, const int* in_sizes, int n_in,
                              void* d_out, int out_size)
{
    const float* x        = (const float*)d_in[0];
    const int*   ei       = (const int*)  d_in[1];
    const float* eattr    = (const float*)d_in[2];
    const float* W1       = (const float*)d_in[3];
    const float* a_src1   = (const float*)d_in[4];
    const float* a_dst1   = (const float*)d_in[5];
    const float* b1       = (const float*)d_in[6];
    const float* W2       = (const float*)d_in[7];
    const float* a_src2   = (const float*)d_in[8];
    const float* a_dst2   = (const float*)d_in[9];
    const float* b2       = (const float*)d_in[10];
    const float* lin_W    = (const float*)d_in[11];
    const float* lin_b    = (const float*)d_in[12];
    const float* mlp_W1   = (const float*)d_in[13];
    const float* mlp_b1   = (const float*)d_in[14];
    const float* mlp_W2   = (const float*)d_in[15];
    const float* mlp_b2   = (const float*)d_in[16];
    float* outp = (float*)d_out;

    const int n = in_sizes[0] / IN_CH;       // 100000
    const int E = in_sizes[1] / 2;           // 1600000

    float *p_xW1, *p_alS1, *p_alD1, *p_h1, *p_xW2, *p_alS2, *p_alD2, *p_h2, *p_h3, *p_A, *p_B;
    int *p_deg, *p_roff, *p_cur, *p_csrc, *p_bsum;
    cudaGetSymbolAddress((void**)&p_xW1,  g_xW1);
    cudaGetSymbolAddress((void**)&p_alS1, g_alS1);
    cudaGetSymbolAddress((void**)&p_alD1, g_alD1);
    cudaGetSymbolAddress((void**)&p_h1,   g_h1);
    cudaGetSymbolAddress((void**)&p_xW2,  g_xW2);
    cudaGetSymbolAddress((void**)&p_alS2, g_alS2);
    cudaGetSymbolAddress((void**)&p_alD2, g_alD2);
    cudaGetSymbolAddress((void**)&p_h2,   g_h2);
    cudaGetSymbolAddress((void**)&p_h3,   g_h3);
    cudaGetSymbolAddress((void**)&p_A,    g_A);
    cudaGetSymbolAddress((void**)&p_B,    g_B);
    cudaGetSymbolAddress((void**)&p_deg,  g_deg);
    cudaGetSymbolAddress((void**)&p_roff, g_roff);
    cudaGetSymbolAddress((void**)&p_cur,  g_cur);
    cudaGetSymbolAddress((void**)&p_csrc, g_csrc);
    cudaGetSymbolAddress((void**)&p_bsum, g_bsum);

    const int gemm_blocks = (n + 127) / 128;
    const int agg_blocks  = (n * 32 + 255) / 256;
    const int e_blocks    = (E + 255) / 256;
    const int mlp_blocks  = 2048;            // grid-stride; weights staged once per block
    const int scan_blocks = (n + 1023) / 1024;   // 98

    // launch #1: zero degree histogram
    zero_kernel<<<(n + 255) / 256, 256>>>(p_deg, n);

    // launch #2: degree histogram
    hist_kernel<<<e_blocks, 256>>>(ei, p_deg, E);

    // launch #3: scan pass 1 (block sums)
    scan_pass1_kernel<<<scan_blocks, 256>>>(p_deg, p_bsum, n);

    // launch #4: GEMM1 — in the ncu capture slot to verify the LDS.128 fix
    // (predict dur 81 -> ~55us, L1% 75.7 -> ~55, fma% 26 -> ~38).
    node_gemm_kernel<128, 64, 1, false><<<gemm_blocks, 256>>>(
        x, W1, nullptr, a_src1, a_dst1, p_xW1, p_alS1, p_alD1, n,
        nullptr, nullptr, nullptr);

    // launch #5: scan pass 2 (roff/cur)
    scan_pass2_kernel<<<scan_blocks, 256>>>(p_deg, p_bsum, p_roff, p_cur, n, scan_blocks);

    // launch #6: scatter sources into CSR
    scatter_kernel<<<e_blocks, 256>>>(ei, p_cur, p_csrc, E);

    // launch #7: GAT layer 1 aggregation
    gat_agg_kernel<8><<<agg_blocks, 256>>>(p_xW1, p_alS1, p_alD1, p_roff, p_csrc, b1, p_h1, n);

    // launch #8: GEMM2
    node_gemm_kernel<64, 64, 2, false><<<gemm_blocks, 256>>>(
        p_h1, W2, nullptr, a_src2, a_dst2, p_xW2, p_alS2, p_alD2, n,
        nullptr, nullptr, nullptr);

    // launch #9: GAT layer 2 aggregation
    gat_agg_kernel<1><<<agg_blocks, 256>>>(p_xW2, p_alS2, p_alD2, p_roff, p_csrc, b2, p_h2, n);

    // launch #10: h3 = h2 @ lin_W + lin_b
    node_gemm_kernel<64, 64, 0, false><<<gemm_blocks, 256>>>(
        p_h2, lin_W, lin_b, nullptr, nullptr, p_h3, nullptr, nullptr, n,
        nullptr, nullptr, nullptr);

    // launch #11: fused A and B GEMMs (gridDim.y = 2)
    node_gemm_kernel<64, 128, 0, true><<<dim3(gemm_blocks, 2), 256>>>(
        p_h3, mlp_W1, mlp_b1, nullptr, nullptr, p_A, nullptr, nullptr, n,
        mlp_W1 + (size_t)64 * 128, nullptr, p_B);

    // launch #12: edge MLP + log_softmax (Wc = mlp_W1 rows 128..143)
    edge_mlp_kernel<<<mlp_blocks, 256>>>(
        ei, eattr, p_A, p_B, mlp_W1 + (size_t)128 * 128, mlp_W2, mlp_b2, outp, E);
}